// round 13
// baseline (speedup 1.0000x reference)
#include <cuda_runtime.h>
#include <float.h>

// Problem shape (fixed by the dataset)
#define BSZ    2
#define SEQ    2048
#define DMODEL 1024
#define NH     16
#define DH     64
#define HIDN   1024
#define MROWS  (BSZ * SEQ)              // 4096

static const long long OUT_ELEMS  = (long long)BSZ * SEQ * DMODEL;   // 4,194,304
static const long long ATTN_ELEMS = (long long)BSZ * NH * SEQ * SEQ; // 134,217,728

// Scratch (allocation-free rule: __device__ globals)
__device__ float g_Q[BSZ * NH * SEQ * DH];
__device__ float g_K[BSZ * NH * SEQ * DH];
__device__ float g_V[BSZ * NH * SEQ * DH];
__device__ float g_mid[BSZ * SEQ * HIDN];
__device__ float g_attn_fb[BSZ * NH * SEQ * SEQ];

// ============================================================================
// gemm128: C = A @ W^T with A[M,K], W[N,K], both K-major. (unchanged, proven)
// MODE 0: C row-major [M,N]
// MODE 1: head-format write C[((b*NH+h)*SEQ+s)*DH + d], m=(b,s), n=(h,d)
// ============================================================================
#define BM 128
#define BN 128
#define BK 8

template <int MODE>
__global__ void __launch_bounds__(256) gemm128_kernel(
    const float* __restrict__ A, const float* __restrict__ W,
    float* __restrict__ C, int M, int N, int K)
{
    __shared__ __align__(16) float As[2][BK][BM];
    __shared__ __align__(16) float Bs[2][BK][BN];

    const int tid   = threadIdx.x;
    const int tx    = tid & 15;
    const int ty    = tid >> 4;
    const int mBase = blockIdx.y * BM;
    const int nBase = blockIdx.x * BN;

    const int lrow = tid >> 1;
    const int lk   = (tid & 1) << 2;

    const float* Ap = A + (size_t)(mBase + lrow) * K + lk;
    const float* Wp = W + (size_t)(nBase + lrow) * K + lk;

    float acc[2][2][4][4] = {};

    {
        float4 a0 = *(const float4*)Ap;
        float4 w0 = *(const float4*)Wp;
        As[0][lk + 0][lrow] = a0.x; As[0][lk + 1][lrow] = a0.y;
        As[0][lk + 2][lrow] = a0.z; As[0][lk + 3][lrow] = a0.w;
        Bs[0][lk + 0][lrow] = w0.x; Bs[0][lk + 1][lrow] = w0.y;
        Bs[0][lk + 2][lrow] = w0.z; Bs[0][lk + 3][lrow] = w0.w;
    }
    __syncthreads();

    int buf = 0;
    for (int k0 = 0; k0 < K; k0 += BK) {
        float4 na, nw;
        const bool more = (k0 + BK) < K;
        if (more) {
            na = *(const float4*)(Ap + k0 + BK);
            nw = *(const float4*)(Wp + k0 + BK);
        }
#pragma unroll
        for (int kk = 0; kk < BK; kk++) {
            float4 a0 = *(const float4*)&As[buf][kk][ty * 4];
            float4 a1 = *(const float4*)&As[buf][kk][ty * 4 + 64];
            float4 b0 = *(const float4*)&Bs[buf][kk][tx * 4];
            float4 b1 = *(const float4*)&Bs[buf][kk][tx * 4 + 64];
            float ar[8] = {a0.x, a0.y, a0.z, a0.w, a1.x, a1.y, a1.z, a1.w};
            float br[8] = {b0.x, b0.y, b0.z, b0.w, b1.x, b1.y, b1.z, b1.w};
#pragma unroll
            for (int ii = 0; ii < 2; ii++)
#pragma unroll
            for (int i = 0; i < 4; i++)
#pragma unroll
            for (int jj = 0; jj < 2; jj++)
#pragma unroll
            for (int j = 0; j < 4; j++)
                acc[ii][jj][i][j] += ar[ii * 4 + i] * br[jj * 4 + j];
        }
        if (more) {
            const int nb = buf ^ 1;
            As[nb][lk + 0][lrow] = na.x; As[nb][lk + 1][lrow] = na.y;
            As[nb][lk + 2][lrow] = na.z; As[nb][lk + 3][lrow] = na.w;
            Bs[nb][lk + 0][lrow] = nw.x; Bs[nb][lk + 1][lrow] = nw.y;
            Bs[nb][lk + 2][lrow] = nw.z; Bs[nb][lk + 3][lrow] = nw.w;
        }
        __syncthreads();
        buf ^= 1;
    }

#pragma unroll
    for (int ii = 0; ii < 2; ii++)
#pragma unroll
    for (int i = 0; i < 4; i++) {
        const int m = mBase + ii * 64 + ty * 4 + i;
#pragma unroll
        for (int jj = 0; jj < 2; jj++) {
            const int n = nBase + jj * 64 + tx * 4;
            float4 v = make_float4(acc[ii][jj][i][0], acc[ii][jj][i][1],
                                   acc[ii][jj][i][2], acc[ii][jj][i][3]);
            if (MODE == 1) {
                const int b_ = m >> 11;
                const int s_ = m & (SEQ - 1);
                const int h_ = n >> 6;
                const int d_ = n & (DH - 1);
                *(float4*)&C[((size_t)(b_ * NH + h_) * SEQ + s_) * DH + d_] = v;
            } else {
                *(float4*)&C[(size_t)m * N + n] = v;
            }
        }
    }
}

// ============================================================================
// Fused attention: per block = 128 rows of one (b,h), full 2048 cols.
//   Phase A (per 128-col chunk): QK^T (8x8 microtile) -> online softmax
//     (running m,s in regs; p=exp(s-m_chunk) stored to gmem attn AND smem)
//     -> AV accumulate with rescale.
//   Phase B: attn *= exp(m_chunk - m_final)/s_final (reread own writes, L2-hot).
//   Writes mid = (AV/s_final) * 1/32 in head-interleaved layout.
// smem layout (floats, dynamic):
//   Qs[64][132], Kc[64][132], Vs[128][68], Ps[128][132], bias[2048], mh[16][128]
// ============================================================================
#define TM   128
#define TC   128
#define KD   64
#define NCH  (SEQ / TC)   // 16

#define QS_OFF   0
#define KC_OFF   (QS_OFF + 64 * 132)        // 8448
#define VS_OFF   (KC_OFF + 64 * 132)        // 16896
#define PS_OFF   (VS_OFF + 128 * 68)        // 25600
#define BIAS_OFF (PS_OFF + 128 * 132)       // 42496
#define MH_OFF   (BIAS_OFF + SEQ)           // 44544
#define FUSED_SMEM_FLOATS (MH_OFF + NCH * TM)   // 46592
#define FUSED_SMEM_BYTES  (FUSED_SMEM_FLOATS * 4) // 186368

__global__ void __launch_bounds__(256, 1) fused_attn_kernel(
    const float* __restrict__ Q, const float* __restrict__ K,
    const float* __restrict__ V, const unsigned char* __restrict__ mask,
    float* __restrict__ attn, float* __restrict__ mid)
{
    extern __shared__ __align__(16) float sm[];
    float* Qs    = sm + QS_OFF;
    float* Kc    = sm + KC_OFF;
    float* Vs    = sm + VS_OFF;
    float* Ps    = sm + PS_OFF;
    float* biass = sm + BIAS_OFF;
    float* mh    = sm + MH_OFF;

    const int bh      = blockIdx.y;
    const int b       = bh >> 4;
    const int h       = bh & 15;
    const int rowBase = blockIdx.x * TM;
    const int tid     = threadIdx.x;
    const int tx      = tid & 15;
    const int ty      = tid >> 4;

    const float* Qg = Q + ((size_t)bh * SEQ + rowBase) * KD;
    const float* Kg = K + (size_t)bh * SEQ * KD;
    const float* Vg = V + (size_t)bh * SEQ * KD;
    float* attnR = attn + ((size_t)bh * SEQ + rowBase) * SEQ;

    // Mask bias (dtype defense: byte vs int32-widened bool)
    {
        const int stride =
            (mask[0] == 1 && mask[1] == 0 && mask[2] == 0 && mask[3] == 0) ? 4 : 1;
        const unsigned char* mb = mask + (size_t)b * SEQ * stride;
        for (int j = tid; j < SEQ; j += 256)
            biass[j] = mb[(size_t)j * stride] ? 0.f : -FLT_MAX;
    }

    // Load Q tile transposed: Qs[k][row], conflict-free (lanes span rows)
    {
        const int r  = tid >> 1;
        const int k4 = (tid & 1) << 2;
        const float* src = Qg + (size_t)r * KD + k4;
#pragma unroll
        for (int t = 0; t < 8; t++) {
            float4 v = *(const float4*)(src + t * 8);
            float* d = Qs + (k4 + t * 8) * 132 + r;
            d[0] = v.x; d[132] = v.y; d[264] = v.z; d[396] = v.w;
        }
    }

    float m_r[2][4], s_r[2][4];
    float oacc[2][4][4] = {};
#pragma unroll
    for (int ii = 0; ii < 2; ii++)
#pragma unroll
    for (int i = 0; i < 4; i++) { m_r[ii][i] = -FLT_MAX; s_r[ii][i] = 0.f; }

    for (int c = 0; c < NCH; c++) {
        __syncthreads();   // previous chunk's consumers done; Qs/bias ready (c=0)

        // Load K chunk transposed Kc[k][col] + V chunk row-major Vs[j][d]
        {
            const int cl = tid >> 1;
            const int k4 = (tid & 1) << 2;
            const float* src = Kg + ((size_t)(c * TC + cl)) * KD + k4;
#pragma unroll
            for (int t = 0; t < 8; t++) {
                float4 v = *(const float4*)(src + t * 8);
                float* d = Kc + (k4 + t * 8) * 132 + cl;
                d[0] = v.x; d[132] = v.y; d[264] = v.z; d[396] = v.w;
            }
#pragma unroll
            for (int t = 0; t < 8; t++) {
                const int f  = tid + t * 256;
                const int vr = f >> 4;
                const int dc = (f & 15) << 2;
                *(float4*)(Vs + vr * 68 + dc) =
                    *(const float4*)(Vg + ((size_t)(c * TC + vr)) * KD + dc);
            }
        }
        __syncthreads();

        // ---- QK^T mainloop (128x128 tile, 8x8 microtile) ----
        float acc[2][2][4][4] = {};
#pragma unroll 8
        for (int kk = 0; kk < KD; kk++) {
            float4 a0 = *(const float4*)(Qs + kk * 132 + ty * 4);
            float4 a1 = *(const float4*)(Qs + kk * 132 + ty * 4 + 64);
            float4 b0 = *(const float4*)(Kc + kk * 132 + tx * 4);
            float4 b1 = *(const float4*)(Kc + kk * 132 + tx * 4 + 64);
            float ar[8] = {a0.x, a0.y, a0.z, a0.w, a1.x, a1.y, a1.z, a1.w};
            float br[8] = {b0.x, b0.y, b0.z, b0.w, b1.x, b1.y, b1.z, b1.w};
#pragma unroll
            for (int ii = 0; ii < 2; ii++)
#pragma unroll
            for (int i = 0; i < 4; i++)
#pragma unroll
            for (int jj = 0; jj < 2; jj++)
#pragma unroll
            for (int j = 0; j < 4; j++)
                acc[ii][jj][i][j] += ar[ii * 4 + i] * br[jj * 4 + j];
        }

        // ---- Online-softmax epilogue ----
        float4 bc0 = *(const float4*)(biass + c * TC + tx * 4);
        float4 bc1 = *(const float4*)(biass + c * TC + tx * 4 + 64);
        const float bb[2][4] = {{bc0.x, bc0.y, bc0.z, bc0.w},
                                {bc1.x, bc1.y, bc1.z, bc1.w}};
#pragma unroll
        for (int ii = 0; ii < 2; ii++)
#pragma unroll
        for (int i = 0; i < 4; i++) {
            const int rloc = ii * 64 + ty * 4 + i;
            float sv[2][4];
            float cmax = -FLT_MAX;
#pragma unroll
            for (int jj = 0; jj < 2; jj++)
#pragma unroll
            for (int j = 0; j < 4; j++) {
                sv[jj][j] = acc[ii][jj][i][j] + bb[jj][j];
                cmax = fmaxf(cmax, sv[jj][j]);
            }
#pragma unroll
            for (int o = 8; o > 0; o >>= 1)
                cmax = fmaxf(cmax, __shfl_xor_sync(0xffffffffu, cmax, o));

            const float mo  = m_r[ii][i];
            const float mn  = fmaxf(mo, cmax);
            const float fac = __expf(mo - mn);

            float p[2][4];
            float rs = 0.f;
#pragma unroll
            for (int jj = 0; jj < 2; jj++)
#pragma unroll
            for (int j = 0; j < 4; j++) {
                p[jj][j] = __expf(sv[jj][j] - mn);
                rs += p[jj][j];
            }
#pragma unroll
            for (int o = 8; o > 0; o >>= 1)
                rs += __shfl_xor_sync(0xffffffffu, rs, o);

            s_r[ii][i] = s_r[ii][i] * fac + rs;
            m_r[ii][i] = mn;
#pragma unroll
            for (int j = 0; j < 4; j++) oacc[ii][i][j] *= fac;

            float4 p0 = make_float4(p[0][0], p[0][1], p[0][2], p[0][3]);
            float4 p1 = make_float4(p[1][0], p[1][1], p[1][2], p[1][3]);
            *(float4*)(Ps + rloc * 132 + tx * 4)      = p0;
            *(float4*)(Ps + rloc * 132 + tx * 4 + 64) = p1;
            *(float4*)(attnR + (size_t)rloc * SEQ + c * TC + tx * 4)      = p0;
            *(float4*)(attnR + (size_t)rloc * SEQ + c * TC + tx * 4 + 64) = p1;
            if (tx == 0) mh[c * TM + rloc] = mn;
        }
        __syncthreads();

        // ---- AV accumulate: oacc += Ps(128x128) @ Vs(128x64) ----
#pragma unroll 4
        for (int kk = 0; kk < TC; kk++) {
            float4 v4 = *(const float4*)(Vs + kk * 68 + tx * 4);
#pragma unroll
            for (int ii = 0; ii < 2; ii++)
#pragma unroll
            for (int i = 0; i < 4; i++) {
                const float a = Ps[(ii * 64 + ty * 4 + i) * 132 + kk];
                oacc[ii][i][0] += a * v4.x;
                oacc[ii][i][1] += a * v4.y;
                oacc[ii][i][2] += a * v4.z;
                oacc[ii][i][3] += a * v4.w;
            }
        }
    }
    __syncthreads();

    // ---- Phase B: normalize stored attn (reread own writes, L2-hot) ----
    float inv_s[2][4];
#pragma unroll
    for (int ii = 0; ii < 2; ii++)
#pragma unroll
    for (int i = 0; i < 4; i++) inv_s[ii][i] = 1.f / s_r[ii][i];

    for (int c = 0; c < NCH; c++) {
#pragma unroll
        for (int ii = 0; ii < 2; ii++)
#pragma unroll
        for (int i = 0; i < 4; i++) {
            const int rloc = ii * 64 + ty * 4 + i;
            const float corr =
                __expf(mh[c * TM + rloc] - m_r[ii][i]) * inv_s[ii][i];
            float* ap = attnR + (size_t)rloc * SEQ + c * TC + tx * 4;
            float4 u0 = *(const float4*)ap;
            float4 u1 = *(const float4*)(ap + 64);
            u0.x *= corr; u0.y *= corr; u0.z *= corr; u0.w *= corr;
            u1.x *= corr; u1.y *= corr; u1.z *= corr; u1.w *= corr;
            *(float4*)ap        = u0;
            *(float4*)(ap + 64) = u1;
        }
    }

    // ---- Write mid = (AV / s_final) * 1/32, head-interleaved ----
#pragma unroll
    for (int ii = 0; ii < 2; ii++)
#pragma unroll
    for (int i = 0; i < 4; i++) {
        const int r = rowBase + ii * 64 + ty * 4 + i;
        const float f = 0.03125f * inv_s[ii][i];
        float4 v = make_float4(oacc[ii][i][0] * f, oacc[ii][i][1] * f,
                               oacc[ii][i][2] * f, oacc[ii][i][3] * f);
        *(float4*)&mid[((size_t)b * SEQ + r) * HIDN + h * DH + tx * 4] = v;
    }
}

extern "C" void kernel_launch(void* const* d_in, const int* in_sizes, int n_in,
                              void* d_out, int out_size)
{
    const float*         x    = (const float*)d_in[0];
    const unsigned char* mask = (const unsigned char*)d_in[1];
    const float*         Wq   = (const float*)d_in[2];
    const float*         Wk   = (const float*)d_in[3];
    const float*         Wv   = (const float*)d_in[4];
    const float*         Wo   = (const float*)d_in[5];
    float* out = (float*)d_out;

    void *pq, *pk, *pv, *pm;
    cudaGetSymbolAddress(&pq, g_Q);
    cudaGetSymbolAddress(&pk, g_K);
    cudaGetSymbolAddress(&pv, g_V);
    cudaGetSymbolAddress(&pm, g_mid);
    float* q   = (float*)pq;
    float* k   = (float*)pk;
    float* v   = (float*)pv;
    float* mid = (float*)pm;

    float* attn;
    if ((long long)out_size >= OUT_ELEMS + ATTN_ELEMS) {
        attn = out + OUT_ELEMS;
    } else {
        void* pa;
        cudaGetSymbolAddress(&pa, g_attn_fb);
        attn = (float*)pa;
    }

    static bool attr_set = false;
    if (!attr_set) {
        cudaFuncSetAttribute(fused_attn_kernel,
                             cudaFuncAttributeMaxDynamicSharedMemorySize,
                             FUSED_SMEM_BYTES);
        attr_set = true;
    }

    dim3 projGrid(HIDN / BN, MROWS / BM);   // (8, 32)
    gemm128_kernel<1><<<projGrid, 256>>>(x, Wq, q, MROWS, HIDN, DMODEL);
    gemm128_kernel<1><<<projGrid, 256>>>(x, Wk, k, MROWS, HIDN, DMODEL);
    gemm128_kernel<1><<<projGrid, 256>>>(x, Wv, v, MROWS, HIDN, DMODEL);

    fused_attn_kernel<<<dim3(SEQ / TM, BSZ * NH), 256, FUSED_SMEM_BYTES>>>(
        q, k, v, mask, attn, mid);

    gemm128_kernel<0><<<dim3(DMODEL / BN, MROWS / BM), 256>>>(
        mid, Wo, out, MROWS, DMODEL, HIDN);
}

// round 14
// speedup vs baseline: 1.0006x; 1.0006x over previous
#include <cuda_runtime.h>
#include <float.h>

// Problem shape (fixed by the dataset)
#define BSZ    2
#define SEQ    2048
#define DMODEL 1024
#define NH     16
#define DH     64
#define HIDN   1024
#define MROWS  (BSZ * SEQ)              // 4096

static const long long OUT_ELEMS  = (long long)BSZ * SEQ * DMODEL;   // 4,194,304
static const long long ATTN_ELEMS = (long long)BSZ * NH * SEQ * SEQ; // 134,217,728

// Scratch (allocation-free rule: __device__ globals)
__device__ float g_Q[BSZ * NH * SEQ * DH];
__device__ float g_K[BSZ * NH * SEQ * DH];
__device__ float g_V[BSZ * NH * SEQ * DH];
__device__ float g_mid[BSZ * SEQ * HIDN];
__device__ float g_attn_fb[BSZ * NH * SEQ * SEQ];

// ============================================================================
// gemm128: C = A @ W^T with A[M,K], W[N,K], both K-major. (unchanged, proven)
// MODE 0: C row-major [M,N]
// MODE 1: head-format write C[((b*NH+h)*SEQ+s)*DH + d], m=(b,s), n=(h,d)
// ============================================================================
#define BM 128
#define BN 128
#define BK 8

template <int MODE>
__global__ void __launch_bounds__(256) gemm128_kernel(
    const float* __restrict__ A, const float* __restrict__ W,
    float* __restrict__ C, int M, int N, int K)
{
    __shared__ __align__(16) float As[2][BK][BM];
    __shared__ __align__(16) float Bs[2][BK][BN];

    const int tid   = threadIdx.x;
    const int tx    = tid & 15;
    const int ty    = tid >> 4;
    const int mBase = blockIdx.y * BM;
    const int nBase = blockIdx.x * BN;

    const int lrow = tid >> 1;
    const int lk   = (tid & 1) << 2;

    const float* Ap = A + (size_t)(mBase + lrow) * K + lk;
    const float* Wp = W + (size_t)(nBase + lrow) * K + lk;

    float acc[2][2][4][4] = {};

    {
        float4 a0 = *(const float4*)Ap;
        float4 w0 = *(const float4*)Wp;
        As[0][lk + 0][lrow] = a0.x; As[0][lk + 1][lrow] = a0.y;
        As[0][lk + 2][lrow] = a0.z; As[0][lk + 3][lrow] = a0.w;
        Bs[0][lk + 0][lrow] = w0.x; Bs[0][lk + 1][lrow] = w0.y;
        Bs[0][lk + 2][lrow] = w0.z; Bs[0][lk + 3][lrow] = w0.w;
    }
    __syncthreads();

    int buf = 0;
    for (int k0 = 0; k0 < K; k0 += BK) {
        float4 na, nw;
        const bool more = (k0 + BK) < K;
        if (more) {
            na = *(const float4*)(Ap + k0 + BK);
            nw = *(const float4*)(Wp + k0 + BK);
        }
#pragma unroll
        for (int kk = 0; kk < BK; kk++) {
            float4 a0 = *(const float4*)&As[buf][kk][ty * 4];
            float4 a1 = *(const float4*)&As[buf][kk][ty * 4 + 64];
            float4 b0 = *(const float4*)&Bs[buf][kk][tx * 4];
            float4 b1 = *(const float4*)&Bs[buf][kk][tx * 4 + 64];
            float ar[8] = {a0.x, a0.y, a0.z, a0.w, a1.x, a1.y, a1.z, a1.w};
            float br[8] = {b0.x, b0.y, b0.z, b0.w, b1.x, b1.y, b1.z, b1.w};
#pragma unroll
            for (int ii = 0; ii < 2; ii++)
#pragma unroll
            for (int i = 0; i < 4; i++)
#pragma unroll
            for (int jj = 0; jj < 2; jj++)
#pragma unroll
            for (int j = 0; j < 4; j++)
                acc[ii][jj][i][j] += ar[ii * 4 + i] * br[jj * 4 + j];
        }
        if (more) {
            const int nb = buf ^ 1;
            As[nb][lk + 0][lrow] = na.x; As[nb][lk + 1][lrow] = na.y;
            As[nb][lk + 2][lrow] = na.z; As[nb][lk + 3][lrow] = na.w;
            Bs[nb][lk + 0][lrow] = nw.x; Bs[nb][lk + 1][lrow] = nw.y;
            Bs[nb][lk + 2][lrow] = nw.z; Bs[nb][lk + 3][lrow] = nw.w;
        }
        __syncthreads();
        buf ^= 1;
    }

#pragma unroll
    for (int ii = 0; ii < 2; ii++)
#pragma unroll
    for (int i = 0; i < 4; i++) {
        const int m = mBase + ii * 64 + ty * 4 + i;
#pragma unroll
        for (int jj = 0; jj < 2; jj++) {
            const int n = nBase + jj * 64 + tx * 4;
            float4 v = make_float4(acc[ii][jj][i][0], acc[ii][jj][i][1],
                                   acc[ii][jj][i][2], acc[ii][jj][i][3]);
            if (MODE == 1) {
                const int b_ = m >> 11;
                const int s_ = m & (SEQ - 1);
                const int h_ = n >> 6;
                const int d_ = n & (DH - 1);
                *(float4*)&C[((size_t)(b_ * NH + h_) * SEQ + s_) * DH + d_] = v;
            } else {
                *(float4*)&C[(size_t)m * N + n] = v;
            }
        }
    }
}

// ============================================================================
// Fused attention: per block = 128 rows of one (b,h), full 2048 cols.
//   Phase A (per 128-col chunk): QK^T (8x8 microtile) -> online softmax
//     (running m,s in regs; p=exp(s-m_chunk) stored to gmem attn AND smem)
//     -> AV accumulate with rescale.
//   Phase B: attn *= exp(m_chunk - m_final)/s_final (reread own writes, L2-hot).
//   Writes mid = (AV/s_final) * 1/32 in head-interleaved layout.
// smem layout (floats, dynamic):
//   Qs[64][132], Kc[64][132], Vs[128][68], Ps[128][132], bias[2048], mh[16][128]
// ============================================================================
#define TM   128
#define TC   128
#define KD   64
#define NCH  (SEQ / TC)   // 16

#define QS_OFF   0
#define KC_OFF   (QS_OFF + 64 * 132)        // 8448
#define VS_OFF   (KC_OFF + 64 * 132)        // 16896
#define PS_OFF   (VS_OFF + 128 * 68)        // 25600
#define BIAS_OFF (PS_OFF + 128 * 132)       // 42496
#define MH_OFF   (BIAS_OFF + SEQ)           // 44544
#define FUSED_SMEM_FLOATS (MH_OFF + NCH * TM)   // 46592
#define FUSED_SMEM_BYTES  (FUSED_SMEM_FLOATS * 4) // 186368

__global__ void __launch_bounds__(256, 1) fused_attn_kernel(
    const float* __restrict__ Q, const float* __restrict__ K,
    const float* __restrict__ V, const unsigned char* __restrict__ mask,
    float* __restrict__ attn, float* __restrict__ mid)
{
    extern __shared__ __align__(16) float sm[];
    float* Qs    = sm + QS_OFF;
    float* Kc    = sm + KC_OFF;
    float* Vs    = sm + VS_OFF;
    float* Ps    = sm + PS_OFF;
    float* biass = sm + BIAS_OFF;
    float* mh    = sm + MH_OFF;

    const int bh      = blockIdx.y;
    const int b       = bh >> 4;
    const int h       = bh & 15;
    const int rowBase = blockIdx.x * TM;
    const int tid     = threadIdx.x;
    const int tx      = tid & 15;
    const int ty      = tid >> 4;

    const float* Qg = Q + ((size_t)bh * SEQ + rowBase) * KD;
    const float* Kg = K + (size_t)bh * SEQ * KD;
    const float* Vg = V + (size_t)bh * SEQ * KD;
    float* attnR = attn + ((size_t)bh * SEQ + rowBase) * SEQ;

    // Mask bias (dtype defense: byte vs int32-widened bool)
    {
        const int stride =
            (mask[0] == 1 && mask[1] == 0 && mask[2] == 0 && mask[3] == 0) ? 4 : 1;
        const unsigned char* mb = mask + (size_t)b * SEQ * stride;
        for (int j = tid; j < SEQ; j += 256)
            biass[j] = mb[(size_t)j * stride] ? 0.f : -FLT_MAX;
    }

    // Load Q tile transposed: Qs[k][row], conflict-free (lanes span rows)
    {
        const int r  = tid >> 1;
        const int k4 = (tid & 1) << 2;
        const float* src = Qg + (size_t)r * KD + k4;
#pragma unroll
        for (int t = 0; t < 8; t++) {
            float4 v = *(const float4*)(src + t * 8);
            float* d = Qs + (k4 + t * 8) * 132 + r;
            d[0] = v.x; d[132] = v.y; d[264] = v.z; d[396] = v.w;
        }
    }

    float m_r[2][4], s_r[2][4];
    float oacc[2][4][4] = {};
#pragma unroll
    for (int ii = 0; ii < 2; ii++)
#pragma unroll
    for (int i = 0; i < 4; i++) { m_r[ii][i] = -FLT_MAX; s_r[ii][i] = 0.f; }

    for (int c = 0; c < NCH; c++) {
        __syncthreads();   // previous chunk's consumers done; Qs/bias ready (c=0)

        // Load K chunk transposed Kc[k][col] + V chunk row-major Vs[j][d]
        {
            const int cl = tid >> 1;
            const int k4 = (tid & 1) << 2;
            const float* src = Kg + ((size_t)(c * TC + cl)) * KD + k4;
#pragma unroll
            for (int t = 0; t < 8; t++) {
                float4 v = *(const float4*)(src + t * 8);
                float* d = Kc + (k4 + t * 8) * 132 + cl;
                d[0] = v.x; d[132] = v.y; d[264] = v.z; d[396] = v.w;
            }
#pragma unroll
            for (int t = 0; t < 8; t++) {
                const int f  = tid + t * 256;
                const int vr = f >> 4;
                const int dc = (f & 15) << 2;
                *(float4*)(Vs + vr * 68 + dc) =
                    *(const float4*)(Vg + ((size_t)(c * TC + vr)) * KD + dc);
            }
        }
        __syncthreads();

        // ---- QK^T mainloop (128x128 tile, 8x8 microtile) ----
        float acc[2][2][4][4] = {};
#pragma unroll 8
        for (int kk = 0; kk < KD; kk++) {
            float4 a0 = *(const float4*)(Qs + kk * 132 + ty * 4);
            float4 a1 = *(const float4*)(Qs + kk * 132 + ty * 4 + 64);
            float4 b0 = *(const float4*)(Kc + kk * 132 + tx * 4);
            float4 b1 = *(const float4*)(Kc + kk * 132 + tx * 4 + 64);
            float ar[8] = {a0.x, a0.y, a0.z, a0.w, a1.x, a1.y, a1.z, a1.w};
            float br[8] = {b0.x, b0.y, b0.z, b0.w, b1.x, b1.y, b1.z, b1.w};
#pragma unroll
            for (int ii = 0; ii < 2; ii++)
#pragma unroll
            for (int i = 0; i < 4; i++)
#pragma unroll
            for (int jj = 0; jj < 2; jj++)
#pragma unroll
            for (int j = 0; j < 4; j++)
                acc[ii][jj][i][j] += ar[ii * 4 + i] * br[jj * 4 + j];
        }

        // ---- Online-softmax epilogue ----
        float4 bc0 = *(const float4*)(biass + c * TC + tx * 4);
        float4 bc1 = *(const float4*)(biass + c * TC + tx * 4 + 64);
        const float bb[2][4] = {{bc0.x, bc0.y, bc0.z, bc0.w},
                                {bc1.x, bc1.y, bc1.z, bc1.w}};
#pragma unroll
        for (int ii = 0; ii < 2; ii++)
#pragma unroll
        for (int i = 0; i < 4; i++) {
            const int rloc = ii * 64 + ty * 4 + i;
            float sv[2][4];
            float cmax = -FLT_MAX;
#pragma unroll
            for (int jj = 0; jj < 2; jj++)
#pragma unroll
            for (int j = 0; j < 4; j++) {
                sv[jj][j] = acc[ii][jj][i][j] + bb[jj][j];
                cmax = fmaxf(cmax, sv[jj][j]);
            }
#pragma unroll
            for (int o = 8; o > 0; o >>= 1)
                cmax = fmaxf(cmax, __shfl_xor_sync(0xffffffffu, cmax, o));

            const float mo  = m_r[ii][i];
            const float mn  = fmaxf(mo, cmax);
            const float fac = __expf(mo - mn);

            float p[2][4];
            float rs = 0.f;
#pragma unroll
            for (int jj = 0; jj < 2; jj++)
#pragma unroll
            for (int j = 0; j < 4; j++) {
                p[jj][j] = __expf(sv[jj][j] - mn);
                rs += p[jj][j];
            }
#pragma unroll
            for (int o = 8; o > 0; o >>= 1)
                rs += __shfl_xor_sync(0xffffffffu, rs, o);

            s_r[ii][i] = s_r[ii][i] * fac + rs;
            m_r[ii][i] = mn;
#pragma unroll
            for (int j = 0; j < 4; j++) oacc[ii][i][j] *= fac;

            float4 p0 = make_float4(p[0][0], p[0][1], p[0][2], p[0][3]);
            float4 p1 = make_float4(p[1][0], p[1][1], p[1][2], p[1][3]);
            *(float4*)(Ps + rloc * 132 + tx * 4)      = p0;
            *(float4*)(Ps + rloc * 132 + tx * 4 + 64) = p1;
            *(float4*)(attnR + (size_t)rloc * SEQ + c * TC + tx * 4)      = p0;
            *(float4*)(attnR + (size_t)rloc * SEQ + c * TC + tx * 4 + 64) = p1;
            if (tx == 0) mh[c * TM + rloc] = mn;
        }
        __syncthreads();

        // ---- AV accumulate: oacc += Ps(128x128) @ Vs(128x64) ----
#pragma unroll 4
        for (int kk = 0; kk < TC; kk++) {
            float4 v4 = *(const float4*)(Vs + kk * 68 + tx * 4);
#pragma unroll
            for (int ii = 0; ii < 2; ii++)
#pragma unroll
            for (int i = 0; i < 4; i++) {
                const float a = Ps[(ii * 64 + ty * 4 + i) * 132 + kk];
                oacc[ii][i][0] += a * v4.x;
                oacc[ii][i][1] += a * v4.y;
                oacc[ii][i][2] += a * v4.z;
                oacc[ii][i][3] += a * v4.w;
            }
        }
    }
    __syncthreads();

    // ---- Phase B: normalize stored attn (reread own writes, L2-hot) ----
    float inv_s[2][4];
#pragma unroll
    for (int ii = 0; ii < 2; ii++)
#pragma unroll
    for (int i = 0; i < 4; i++) inv_s[ii][i] = 1.f / s_r[ii][i];

    for (int c = 0; c < NCH; c++) {
#pragma unroll
        for (int ii = 0; ii < 2; ii++)
#pragma unroll
        for (int i = 0; i < 4; i++) {
            const int rloc = ii * 64 + ty * 4 + i;
            const float corr =
                __expf(mh[c * TM + rloc] - m_r[ii][i]) * inv_s[ii][i];
            float* ap = attnR + (size_t)rloc * SEQ + c * TC + tx * 4;
            float4 u0 = *(const float4*)ap;
            float4 u1 = *(const float4*)(ap + 64);
            u0.x *= corr; u0.y *= corr; u0.z *= corr; u0.w *= corr;
            u1.x *= corr; u1.y *= corr; u1.z *= corr; u1.w *= corr;
            *(float4*)ap        = u0;
            *(float4*)(ap + 64) = u1;
        }
    }

    // ---- Write mid = (AV / s_final) * 1/32, head-interleaved ----
#pragma unroll
    for (int ii = 0; ii < 2; ii++)
#pragma unroll
    for (int i = 0; i < 4; i++) {
        const int r = rowBase + ii * 64 + ty * 4 + i;
        const float f = 0.03125f * inv_s[ii][i];
        float4 v = make_float4(oacc[ii][i][0] * f, oacc[ii][i][1] * f,
                               oacc[ii][i][2] * f, oacc[ii][i][3] * f);
        *(float4*)&mid[((size_t)b * SEQ + r) * HIDN + h * DH + tx * 4] = v;
    }
}

extern "C" void kernel_launch(void* const* d_in, const int* in_sizes, int n_in,
                              void* d_out, int out_size)
{
    const float*         x    = (const float*)d_in[0];
    const unsigned char* mask = (const unsigned char*)d_in[1];
    const float*         Wq   = (const float*)d_in[2];
    const float*         Wk   = (const float*)d_in[3];
    const float*         Wv   = (const float*)d_in[4];
    const float*         Wo   = (const float*)d_in[5];
    float* out = (float*)d_out;

    void *pq, *pk, *pv, *pm;
    cudaGetSymbolAddress(&pq, g_Q);
    cudaGetSymbolAddress(&pk, g_K);
    cudaGetSymbolAddress(&pv, g_V);
    cudaGetSymbolAddress(&pm, g_mid);
    float* q   = (float*)pq;
    float* k   = (float*)pk;
    float* v   = (float*)pv;
    float* mid = (float*)pm;

    float* attn;
    if ((long long)out_size >= OUT_ELEMS + ATTN_ELEMS) {
        attn = out + OUT_ELEMS;
    } else {
        void* pa;
        cudaGetSymbolAddress(&pa, g_attn_fb);
        attn = (float*)pa;
    }

    static bool attr_set = false;
    if (!attr_set) {
        cudaFuncSetAttribute(fused_attn_kernel,
                             cudaFuncAttributeMaxDynamicSharedMemorySize,
                             FUSED_SMEM_BYTES);
        attr_set = true;
    }

    dim3 projGrid(HIDN / BN, MROWS / BM);   // (8, 32)
    gemm128_kernel<1><<<projGrid, 256>>>(x, Wq, q, MROWS, HIDN, DMODEL);
    gemm128_kernel<1><<<projGrid, 256>>>(x, Wk, k, MROWS, HIDN, DMODEL);
    gemm128_kernel<1><<<projGrid, 256>>>(x, Wv, v, MROWS, HIDN, DMODEL);

    fused_attn_kernel<<<dim3(SEQ / TM, BSZ * NH), 256, FUSED_SMEM_BYTES>>>(
        q, k, v, mask, attn, mid);

    gemm128_kernel<0><<<dim3(DMODEL / BN, MROWS / BM), 256>>>(
        mid, Wo, out, MROWS, DMODEL, HIDN);
}

// round 15
// speedup vs baseline: 1.0492x; 1.0486x over previous
#include <cuda_runtime.h>
#include <float.h>

// Problem shape (fixed by the dataset)
#define BSZ    2
#define SEQ    2048
#define DMODEL 1024
#define NH     16
#define DH     64
#define HIDN   1024
#define MROWS  (BSZ * SEQ)              // 4096

static const long long OUT_ELEMS  = (long long)BSZ * SEQ * DMODEL;   // 4,194,304
static const long long ATTN_ELEMS = (long long)BSZ * NH * SEQ * SEQ; // 134,217,728

// Scratch (allocation-free rule: __device__ globals)
__device__ float g_Q[BSZ * NH * SEQ * DH];
__device__ float g_K[BSZ * NH * SEQ * DH];
__device__ float g_V[BSZ * NH * SEQ * DH];
__device__ float g_mid[BSZ * SEQ * HIDN];
__device__ float g_attn_fb[BSZ * NH * SEQ * SEQ];

// ============================================================================
// gemm128: C = A @ W^T with A[M,K], W[N,K], both K-major. (unchanged, proven)
// MODE 0: C row-major [M,N]
// MODE 1: head-format write C[((b*NH+h)*SEQ+s)*DH + d], m=(b,s), n=(h,d)
// ============================================================================
#define BM 128
#define BN 128
#define BK 8

template <int MODE>
__global__ void __launch_bounds__(256) gemm128_kernel(
    const float* __restrict__ A, const float* __restrict__ W,
    float* __restrict__ C, int M, int N, int K)
{
    __shared__ __align__(16) float As[2][BK][BM];
    __shared__ __align__(16) float Bs[2][BK][BN];

    const int tid   = threadIdx.x;
    const int tx    = tid & 15;
    const int ty    = tid >> 4;
    const int mBase = blockIdx.y * BM;
    const int nBase = blockIdx.x * BN;

    const int lrow = tid >> 1;
    const int lk   = (tid & 1) << 2;

    const float* Ap = A + (size_t)(mBase + lrow) * K + lk;
    const float* Wp = W + (size_t)(nBase + lrow) * K + lk;

    float acc[2][2][4][4] = {};

    {
        float4 a0 = *(const float4*)Ap;
        float4 w0 = *(const float4*)Wp;
        As[0][lk + 0][lrow] = a0.x; As[0][lk + 1][lrow] = a0.y;
        As[0][lk + 2][lrow] = a0.z; As[0][lk + 3][lrow] = a0.w;
        Bs[0][lk + 0][lrow] = w0.x; Bs[0][lk + 1][lrow] = w0.y;
        Bs[0][lk + 2][lrow] = w0.z; Bs[0][lk + 3][lrow] = w0.w;
    }
    __syncthreads();

    int buf = 0;
    for (int k0 = 0; k0 < K; k0 += BK) {
        float4 na, nw;
        const bool more = (k0 + BK) < K;
        if (more) {
            na = *(const float4*)(Ap + k0 + BK);
            nw = *(const float4*)(Wp + k0 + BK);
        }
#pragma unroll
        for (int kk = 0; kk < BK; kk++) {
            float4 a0 = *(const float4*)&As[buf][kk][ty * 4];
            float4 a1 = *(const float4*)&As[buf][kk][ty * 4 + 64];
            float4 b0 = *(const float4*)&Bs[buf][kk][tx * 4];
            float4 b1 = *(const float4*)&Bs[buf][kk][tx * 4 + 64];
            float ar[8] = {a0.x, a0.y, a0.z, a0.w, a1.x, a1.y, a1.z, a1.w};
            float br[8] = {b0.x, b0.y, b0.z, b0.w, b1.x, b1.y, b1.z, b1.w};
#pragma unroll
            for (int ii = 0; ii < 2; ii++)
#pragma unroll
            for (int i = 0; i < 4; i++)
#pragma unroll
            for (int jj = 0; jj < 2; jj++)
#pragma unroll
            for (int j = 0; j < 4; j++)
                acc[ii][jj][i][j] += ar[ii * 4 + i] * br[jj * 4 + j];
        }
        if (more) {
            const int nb = buf ^ 1;
            As[nb][lk + 0][lrow] = na.x; As[nb][lk + 1][lrow] = na.y;
            As[nb][lk + 2][lrow] = na.z; As[nb][lk + 3][lrow] = na.w;
            Bs[nb][lk + 0][lrow] = nw.x; Bs[nb][lk + 1][lrow] = nw.y;
            Bs[nb][lk + 2][lrow] = nw.z; Bs[nb][lk + 3][lrow] = nw.w;
        }
        __syncthreads();
        buf ^= 1;
    }

#pragma unroll
    for (int ii = 0; ii < 2; ii++)
#pragma unroll
    for (int i = 0; i < 4; i++) {
        const int m = mBase + ii * 64 + ty * 4 + i;
#pragma unroll
        for (int jj = 0; jj < 2; jj++) {
            const int n = nBase + jj * 64 + tx * 4;
            float4 v = make_float4(acc[ii][jj][i][0], acc[ii][jj][i][1],
                                   acc[ii][jj][i][2], acc[ii][jj][i][3]);
            if (MODE == 1) {
                const int b_ = m >> 11;
                const int s_ = m & (SEQ - 1);
                const int h_ = n >> 6;
                const int d_ = n & (DH - 1);
                *(float4*)&C[((size_t)(b_ * NH + h_) * SEQ + s_) * DH + d_] = v;
            } else {
                *(float4*)&C[(size_t)m * N + n] = v;
            }
        }
    }
}

// ============================================================================
// Fused attention: per block = 128 rows of one (b,h), full 2048 cols.
//   Phase A (per 128-col chunk): QK^T (8x8 microtile) -> online softmax
//     (running m,s in regs; p=exp(s-m_chunk) stored to gmem attn AND smem)
//     -> AV accumulate with rescale.
//   Phase B: attn *= exp(m_chunk - m_final)/s_final (reread own writes, L2-hot).
//   Writes mid = (AV/s_final) * 1/32 in head-interleaved layout.
// smem layout (floats, dynamic):
//   Qs[64][132], Kc[64][132], Vs[128][68], Ps[128][132], bias[2048], mh[16][128]
// ============================================================================
#define TM   128
#define TC   128
#define KD   64
#define NCH  (SEQ / TC)   // 16

#define QS_OFF   0
#define KC_OFF   (QS_OFF + 64 * 132)        // 8448
#define VS_OFF   (KC_OFF + 64 * 132)        // 16896
#define PS_OFF   (VS_OFF + 128 * 68)        // 25600
#define BIAS_OFF (PS_OFF + 128 * 132)       // 42496
#define MH_OFF   (BIAS_OFF + SEQ)           // 44544
#define FUSED_SMEM_FLOATS (MH_OFF + NCH * TM)   // 46592
#define FUSED_SMEM_BYTES  (FUSED_SMEM_FLOATS * 4) // 186368

__global__ void __launch_bounds__(256, 1) fused_attn_kernel(
    const float* __restrict__ Q, const float* __restrict__ K,
    const float* __restrict__ V, const unsigned char* __restrict__ mask,
    float* __restrict__ attn, float* __restrict__ mid)
{
    extern __shared__ __align__(16) float sm[];
    float* Qs    = sm + QS_OFF;
    float* Kc    = sm + KC_OFF;
    float* Vs    = sm + VS_OFF;
    float* Ps    = sm + PS_OFF;
    float* biass = sm + BIAS_OFF;
    float* mh    = sm + MH_OFF;

    const int bh      = blockIdx.y;
    const int b       = bh >> 4;
    const int h       = bh & 15;
    const int rowBase = blockIdx.x * TM;
    const int tid     = threadIdx.x;
    const int tx      = tid & 15;
    const int ty      = tid >> 4;

    const float* Qg = Q + ((size_t)bh * SEQ + rowBase) * KD;
    const float* Kg = K + (size_t)bh * SEQ * KD;
    const float* Vg = V + (size_t)bh * SEQ * KD;
    float* attnR = attn + ((size_t)bh * SEQ + rowBase) * SEQ;

    // Mask bias (dtype defense: byte vs int32-widened bool)
    {
        const int stride =
            (mask[0] == 1 && mask[1] == 0 && mask[2] == 0 && mask[3] == 0) ? 4 : 1;
        const unsigned char* mb = mask + (size_t)b * SEQ * stride;
        for (int j = tid; j < SEQ; j += 256)
            biass[j] = mb[(size_t)j * stride] ? 0.f : -FLT_MAX;
    }

    // Load Q tile transposed: Qs[k][row], conflict-free (lanes span rows)
    {
        const int r  = tid >> 1;
        const int k4 = (tid & 1) << 2;
        const float* src = Qg + (size_t)r * KD + k4;
#pragma unroll
        for (int t = 0; t < 8; t++) {
            float4 v = *(const float4*)(src + t * 8);
            float* d = Qs + (k4 + t * 8) * 132 + r;
            d[0] = v.x; d[132] = v.y; d[264] = v.z; d[396] = v.w;
        }
    }

    float m_r[2][4], s_r[2][4];
    float oacc[2][4][4] = {};
#pragma unroll
    for (int ii = 0; ii < 2; ii++)
#pragma unroll
    for (int i = 0; i < 4; i++) { m_r[ii][i] = -FLT_MAX; s_r[ii][i] = 0.f; }

    for (int c = 0; c < NCH; c++) {
        __syncthreads();   // previous chunk's consumers done; Qs/bias ready (c=0)

        // Load K chunk transposed Kc[k][col] + V chunk row-major Vs[j][d]
        {
            const int cl = tid >> 1;
            const int k4 = (tid & 1) << 2;
            const float* src = Kg + ((size_t)(c * TC + cl)) * KD + k4;
#pragma unroll
            for (int t = 0; t < 8; t++) {
                float4 v = *(const float4*)(src + t * 8);
                float* d = Kc + (k4 + t * 8) * 132 + cl;
                d[0] = v.x; d[132] = v.y; d[264] = v.z; d[396] = v.w;
            }
#pragma unroll
            for (int t = 0; t < 8; t++) {
                const int f  = tid + t * 256;
                const int vr = f >> 4;
                const int dc = (f & 15) << 2;
                *(float4*)(Vs + vr * 68 + dc) =
                    *(const float4*)(Vg + ((size_t)(c * TC + vr)) * KD + dc);
            }
        }
        __syncthreads();

        // ---- QK^T mainloop (128x128 tile, 8x8 microtile) ----
        float acc[2][2][4][4] = {};
#pragma unroll 8
        for (int kk = 0; kk < KD; kk++) {
            float4 a0 = *(const float4*)(Qs + kk * 132 + ty * 4);
            float4 a1 = *(const float4*)(Qs + kk * 132 + ty * 4 + 64);
            float4 b0 = *(const float4*)(Kc + kk * 132 + tx * 4);
            float4 b1 = *(const float4*)(Kc + kk * 132 + tx * 4 + 64);
            float ar[8] = {a0.x, a0.y, a0.z, a0.w, a1.x, a1.y, a1.z, a1.w};
            float br[8] = {b0.x, b0.y, b0.z, b0.w, b1.x, b1.y, b1.z, b1.w};
#pragma unroll
            for (int ii = 0; ii < 2; ii++)
#pragma unroll
            for (int i = 0; i < 4; i++)
#pragma unroll
            for (int jj = 0; jj < 2; jj++)
#pragma unroll
            for (int j = 0; j < 4; j++)
                acc[ii][jj][i][j] += ar[ii * 4 + i] * br[jj * 4 + j];
        }

        // ---- Online-softmax epilogue ----
        float4 bc0 = *(const float4*)(biass + c * TC + tx * 4);
        float4 bc1 = *(const float4*)(biass + c * TC + tx * 4 + 64);
        const float bb[2][4] = {{bc0.x, bc0.y, bc0.z, bc0.w},
                                {bc1.x, bc1.y, bc1.z, bc1.w}};
#pragma unroll
        for (int ii = 0; ii < 2; ii++)
#pragma unroll
        for (int i = 0; i < 4; i++) {
            const int rloc = ii * 64 + ty * 4 + i;
            float sv[2][4];
            float cmax = -FLT_MAX;
#pragma unroll
            for (int jj = 0; jj < 2; jj++)
#pragma unroll
            for (int j = 0; j < 4; j++) {
                sv[jj][j] = acc[ii][jj][i][j] + bb[jj][j];
                cmax = fmaxf(cmax, sv[jj][j]);
            }
#pragma unroll
            for (int o = 8; o > 0; o >>= 1)
                cmax = fmaxf(cmax, __shfl_xor_sync(0xffffffffu, cmax, o));

            const float mo  = m_r[ii][i];
            const float mn  = fmaxf(mo, cmax);
            const float fac = __expf(mo - mn);

            float p[2][4];
            float rs = 0.f;
#pragma unroll
            for (int jj = 0; jj < 2; jj++)
#pragma unroll
            for (int j = 0; j < 4; j++) {
                p[jj][j] = __expf(sv[jj][j] - mn);
                rs += p[jj][j];
            }
#pragma unroll
            for (int o = 8; o > 0; o >>= 1)
                rs += __shfl_xor_sync(0xffffffffu, rs, o);

            s_r[ii][i] = s_r[ii][i] * fac + rs;
            m_r[ii][i] = mn;
#pragma unroll
            for (int j = 0; j < 4; j++) oacc[ii][i][j] *= fac;

            float4 p0 = make_float4(p[0][0], p[0][1], p[0][2], p[0][3]);
            float4 p1 = make_float4(p[1][0], p[1][1], p[1][2], p[1][3]);
            *(float4*)(Ps + rloc * 132 + tx * 4)      = p0;
            *(float4*)(Ps + rloc * 132 + tx * 4 + 64) = p1;
            *(float4*)(attnR + (size_t)rloc * SEQ + c * TC + tx * 4)      = p0;
            *(float4*)(attnR + (size_t)rloc * SEQ + c * TC + tx * 4 + 64) = p1;
            if (tx == 0) mh[c * TM + rloc] = mn;
        }
        __syncthreads();

        // ---- AV accumulate: oacc += Ps(128x128) @ Vs(128x64) ----
#pragma unroll 4
        for (int kk = 0; kk < TC; kk++) {
            float4 v4 = *(const float4*)(Vs + kk * 68 + tx * 4);
#pragma unroll
            for (int ii = 0; ii < 2; ii++)
#pragma unroll
            for (int i = 0; i < 4; i++) {
                const float a = Ps[(ii * 64 + ty * 4 + i) * 132 + kk];
                oacc[ii][i][0] += a * v4.x;
                oacc[ii][i][1] += a * v4.y;
                oacc[ii][i][2] += a * v4.z;
                oacc[ii][i][3] += a * v4.w;
            }
        }
    }
    __syncthreads();

    // ---- Phase B: normalize stored attn (reread own writes, L2-hot) ----
    float inv_s[2][4];
#pragma unroll
    for (int ii = 0; ii < 2; ii++)
#pragma unroll
    for (int i = 0; i < 4; i++) inv_s[ii][i] = 1.f / s_r[ii][i];

    for (int c = 0; c < NCH; c++) {
#pragma unroll
        for (int ii = 0; ii < 2; ii++)
#pragma unroll
        for (int i = 0; i < 4; i++) {
            const int rloc = ii * 64 + ty * 4 + i;
            const float corr =
                __expf(mh[c * TM + rloc] - m_r[ii][i]) * inv_s[ii][i];
            float* ap = attnR + (size_t)rloc * SEQ + c * TC + tx * 4;
            float4 u0 = *(const float4*)ap;
            float4 u1 = *(const float4*)(ap + 64);
            u0.x *= corr; u0.y *= corr; u0.z *= corr; u0.w *= corr;
            u1.x *= corr; u1.y *= corr; u1.z *= corr; u1.w *= corr;
            *(float4*)ap        = u0;
            *(float4*)(ap + 64) = u1;
        }
    }

    // ---- Write mid = (AV / s_final) * 1/32, head-interleaved ----
#pragma unroll
    for (int ii = 0; ii < 2; ii++)
#pragma unroll
    for (int i = 0; i < 4; i++) {
        const int r = rowBase + ii * 64 + ty * 4 + i;
        const float f = 0.03125f * inv_s[ii][i];
        float4 v = make_float4(oacc[ii][i][0] * f, oacc[ii][i][1] * f,
                               oacc[ii][i][2] * f, oacc[ii][i][3] * f);
        *(float4*)&mid[((size_t)b * SEQ + r) * HIDN + h * DH + tx * 4] = v;
    }
}

extern "C" void kernel_launch(void* const* d_in, const int* in_sizes, int n_in,
                              void* d_out, int out_size)
{
    const float*         x    = (const float*)d_in[0];
    const unsigned char* mask = (const unsigned char*)d_in[1];
    const float*         Wq   = (const float*)d_in[2];
    const float*         Wk   = (const float*)d_in[3];
    const float*         Wv   = (const float*)d_in[4];
    const float*         Wo   = (const float*)d_in[5];
    float* out = (float*)d_out;

    void *pq, *pk, *pv, *pm;
    cudaGetSymbolAddress(&pq, g_Q);
    cudaGetSymbolAddress(&pk, g_K);
    cudaGetSymbolAddress(&pv, g_V);
    cudaGetSymbolAddress(&pm, g_mid);
    float* q   = (float*)pq;
    float* k   = (float*)pk;
    float* v   = (float*)pv;
    float* mid = (float*)pm;

    float* attn;
    if ((long long)out_size >= OUT_ELEMS + ATTN_ELEMS) {
        attn = out + OUT_ELEMS;
    } else {
        void* pa;
        cudaGetSymbolAddress(&pa, g_attn_fb);
        attn = (float*)pa;
    }

    static bool attr_set = false;
    if (!attr_set) {
        cudaFuncSetAttribute(fused_attn_kernel,
                             cudaFuncAttributeMaxDynamicSharedMemorySize,
                             FUSED_SMEM_BYTES);
        attr_set = true;
    }

    dim3 projGrid(HIDN / BN, MROWS / BM);   // (8, 32)
    gemm128_kernel<1><<<projGrid, 256>>>(x, Wq, q, MROWS, HIDN, DMODEL);
    gemm128_kernel<1><<<projGrid, 256>>>(x, Wk, k, MROWS, HIDN, DMODEL);
    gemm128_kernel<1><<<projGrid, 256>>>(x, Wv, v, MROWS, HIDN, DMODEL);

    fused_attn_kernel<<<dim3(SEQ / TM, BSZ * NH), 256, FUSED_SMEM_BYTES>>>(
        q, k, v, mask, attn, mid);

    gemm128_kernel<0><<<dim3(DMODEL / BN, MROWS / BM), 256>>>(
        mid, Wo, out, MROWS, DMODEL, HIDN);
}

// round 16
// speedup vs baseline: 1.0499x; 1.0007x over previous
#include <cuda_runtime.h>
#include <float.h>

// Problem shape (fixed by the dataset)
#define BSZ    2
#define SEQ    2048
#define DMODEL 1024
#define NH     16
#define DH     64
#define HIDN   1024
#define MROWS  (BSZ * SEQ)              // 4096

static const long long OUT_ELEMS  = (long long)BSZ * SEQ * DMODEL;   // 4,194,304
static const long long ATTN_ELEMS = (long long)BSZ * NH * SEQ * SEQ; // 134,217,728

// Scratch (allocation-free rule: __device__ globals)
__device__ float g_Q[BSZ * NH * SEQ * DH];
__device__ float g_K[BSZ * NH * SEQ * DH];
__device__ float g_V[BSZ * NH * SEQ * DH];
__device__ float g_mid[BSZ * SEQ * HIDN];
__device__ float g_attn_fb[BSZ * NH * SEQ * SEQ];

// ============================================================================
// gemm128: C = A @ W^T with A[M,K], W[N,K], both K-major. (unchanged, proven)
// MODE 0: C row-major [M,N]
// MODE 1: head-format write C[((b*NH+h)*SEQ+s)*DH + d], m=(b,s), n=(h,d)
// ============================================================================
#define BM 128
#define BN 128
#define BK 8

template <int MODE>
__global__ void __launch_bounds__(256) gemm128_kernel(
    const float* __restrict__ A, const float* __restrict__ W,
    float* __restrict__ C, int M, int N, int K)
{
    __shared__ __align__(16) float As[2][BK][BM];
    __shared__ __align__(16) float Bs[2][BK][BN];

    const int tid   = threadIdx.x;
    const int tx    = tid & 15;
    const int ty    = tid >> 4;
    const int mBase = blockIdx.y * BM;
    const int nBase = blockIdx.x * BN;

    const int lrow = tid >> 1;
    const int lk   = (tid & 1) << 2;

    const float* Ap = A + (size_t)(mBase + lrow) * K + lk;
    const float* Wp = W + (size_t)(nBase + lrow) * K + lk;

    float acc[2][2][4][4] = {};

    {
        float4 a0 = *(const float4*)Ap;
        float4 w0 = *(const float4*)Wp;
        As[0][lk + 0][lrow] = a0.x; As[0][lk + 1][lrow] = a0.y;
        As[0][lk + 2][lrow] = a0.z; As[0][lk + 3][lrow] = a0.w;
        Bs[0][lk + 0][lrow] = w0.x; Bs[0][lk + 1][lrow] = w0.y;
        Bs[0][lk + 2][lrow] = w0.z; Bs[0][lk + 3][lrow] = w0.w;
    }
    __syncthreads();

    int buf = 0;
    for (int k0 = 0; k0 < K; k0 += BK) {
        float4 na, nw;
        const bool more = (k0 + BK) < K;
        if (more) {
            na = *(const float4*)(Ap + k0 + BK);
            nw = *(const float4*)(Wp + k0 + BK);
        }
#pragma unroll
        for (int kk = 0; kk < BK; kk++) {
            float4 a0 = *(const float4*)&As[buf][kk][ty * 4];
            float4 a1 = *(const float4*)&As[buf][kk][ty * 4 + 64];
            float4 b0 = *(const float4*)&Bs[buf][kk][tx * 4];
            float4 b1 = *(const float4*)&Bs[buf][kk][tx * 4 + 64];
            float ar[8] = {a0.x, a0.y, a0.z, a0.w, a1.x, a1.y, a1.z, a1.w};
            float br[8] = {b0.x, b0.y, b0.z, b0.w, b1.x, b1.y, b1.z, b1.w};
#pragma unroll
            for (int ii = 0; ii < 2; ii++)
#pragma unroll
            for (int i = 0; i < 4; i++)
#pragma unroll
            for (int jj = 0; jj < 2; jj++)
#pragma unroll
            for (int j = 0; j < 4; j++)
                acc[ii][jj][i][j] += ar[ii * 4 + i] * br[jj * 4 + j];
        }
        if (more) {
            const int nb = buf ^ 1;
            As[nb][lk + 0][lrow] = na.x; As[nb][lk + 1][lrow] = na.y;
            As[nb][lk + 2][lrow] = na.z; As[nb][lk + 3][lrow] = na.w;
            Bs[nb][lk + 0][lrow] = nw.x; Bs[nb][lk + 1][lrow] = nw.y;
            Bs[nb][lk + 2][lrow] = nw.z; Bs[nb][lk + 3][lrow] = nw.w;
        }
        __syncthreads();
        buf ^= 1;
    }

#pragma unroll
    for (int ii = 0; ii < 2; ii++)
#pragma unroll
    for (int i = 0; i < 4; i++) {
        const int m = mBase + ii * 64 + ty * 4 + i;
#pragma unroll
        for (int jj = 0; jj < 2; jj++) {
            const int n = nBase + jj * 64 + tx * 4;
            float4 v = make_float4(acc[ii][jj][i][0], acc[ii][jj][i][1],
                                   acc[ii][jj][i][2], acc[ii][jj][i][3]);
            if (MODE == 1) {
                const int b_ = m >> 11;
                const int s_ = m & (SEQ - 1);
                const int h_ = n >> 6;
                const int d_ = n & (DH - 1);
                *(float4*)&C[((size_t)(b_ * NH + h_) * SEQ + s_) * DH + d_] = v;
            } else {
                *(float4*)&C[(size_t)m * N + n] = v;
            }
        }
    }
}

// ============================================================================
// Fused attention: per block = 128 rows of one (b,h), full 2048 cols.
//   Phase A (per 128-col chunk): QK^T (8x8 microtile) -> online softmax
//     (running m,s in regs; p=exp(s-m_chunk) stored to gmem attn AND smem)
//     -> AV accumulate with rescale.
//   Phase B: attn *= exp(m_chunk - m_final)/s_final (reread own writes, L2-hot).
//   Writes mid = (AV/s_final) * 1/32 in head-interleaved layout.
// smem layout (floats, dynamic):
//   Qs[64][132], Kc[64][132], Vs[128][68], Ps[128][132], bias[2048], mh[16][128]
// ============================================================================
#define TM   128
#define TC   128
#define KD   64
#define NCH  (SEQ / TC)   // 16

#define QS_OFF   0
#define KC_OFF   (QS_OFF + 64 * 132)        // 8448
#define VS_OFF   (KC_OFF + 64 * 132)        // 16896
#define PS_OFF   (VS_OFF + 128 * 68)        // 25600
#define BIAS_OFF (PS_OFF + 128 * 132)       // 42496
#define MH_OFF   (BIAS_OFF + SEQ)           // 44544
#define FUSED_SMEM_FLOATS (MH_OFF + NCH * TM)   // 46592
#define FUSED_SMEM_BYTES  (FUSED_SMEM_FLOATS * 4) // 186368

__global__ void __launch_bounds__(256, 1) fused_attn_kernel(
    const float* __restrict__ Q, const float* __restrict__ K,
    const float* __restrict__ V, const unsigned char* __restrict__ mask,
    float* __restrict__ attn, float* __restrict__ mid)
{
    extern __shared__ __align__(16) float sm[];
    float* Qs    = sm + QS_OFF;
    float* Kc    = sm + KC_OFF;
    float* Vs    = sm + VS_OFF;
    float* Ps    = sm + PS_OFF;
    float* biass = sm + BIAS_OFF;
    float* mh    = sm + MH_OFF;

    const int bh      = blockIdx.y;
    const int b       = bh >> 4;
    const int h       = bh & 15;
    const int rowBase = blockIdx.x * TM;
    const int tid     = threadIdx.x;
    const int tx      = tid & 15;
    const int ty      = tid >> 4;

    const float* Qg = Q + ((size_t)bh * SEQ + rowBase) * KD;
    const float* Kg = K + (size_t)bh * SEQ * KD;
    const float* Vg = V + (size_t)bh * SEQ * KD;
    float* attnR = attn + ((size_t)bh * SEQ + rowBase) * SEQ;

    // Mask bias (dtype defense: byte vs int32-widened bool)
    {
        const int stride =
            (mask[0] == 1 && mask[1] == 0 && mask[2] == 0 && mask[3] == 0) ? 4 : 1;
        const unsigned char* mb = mask + (size_t)b * SEQ * stride;
        for (int j = tid; j < SEQ; j += 256)
            biass[j] = mb[(size_t)j * stride] ? 0.f : -FLT_MAX;
    }

    // Load Q tile transposed: Qs[k][row], conflict-free (lanes span rows)
    {
        const int r  = tid >> 1;
        const int k4 = (tid & 1) << 2;
        const float* src = Qg + (size_t)r * KD + k4;
#pragma unroll
        for (int t = 0; t < 8; t++) {
            float4 v = *(const float4*)(src + t * 8);
            float* d = Qs + (k4 + t * 8) * 132 + r;
            d[0] = v.x; d[132] = v.y; d[264] = v.z; d[396] = v.w;
        }
    }

    float m_r[2][4], s_r[2][4];
    float oacc[2][4][4] = {};
#pragma unroll
    for (int ii = 0; ii < 2; ii++)
#pragma unroll
    for (int i = 0; i < 4; i++) { m_r[ii][i] = -FLT_MAX; s_r[ii][i] = 0.f; }

    for (int c = 0; c < NCH; c++) {
        __syncthreads();   // previous chunk's consumers done; Qs/bias ready (c=0)

        // Load K chunk transposed Kc[k][col] + V chunk row-major Vs[j][d]
        {
            const int cl = tid >> 1;
            const int k4 = (tid & 1) << 2;
            const float* src = Kg + ((size_t)(c * TC + cl)) * KD + k4;
#pragma unroll
            for (int t = 0; t < 8; t++) {
                float4 v = *(const float4*)(src + t * 8);
                float* d = Kc + (k4 + t * 8) * 132 + cl;
                d[0] = v.x; d[132] = v.y; d[264] = v.z; d[396] = v.w;
            }
#pragma unroll
            for (int t = 0; t < 8; t++) {
                const int f  = tid + t * 256;
                const int vr = f >> 4;
                const int dc = (f & 15) << 2;
                *(float4*)(Vs + vr * 68 + dc) =
                    *(const float4*)(Vg + ((size_t)(c * TC + vr)) * KD + dc);
            }
        }
        __syncthreads();

        // ---- QK^T mainloop (128x128 tile, 8x8 microtile) ----
        float acc[2][2][4][4] = {};
#pragma unroll 8
        for (int kk = 0; kk < KD; kk++) {
            float4 a0 = *(const float4*)(Qs + kk * 132 + ty * 4);
            float4 a1 = *(const float4*)(Qs + kk * 132 + ty * 4 + 64);
            float4 b0 = *(const float4*)(Kc + kk * 132 + tx * 4);
            float4 b1 = *(const float4*)(Kc + kk * 132 + tx * 4 + 64);
            float ar[8] = {a0.x, a0.y, a0.z, a0.w, a1.x, a1.y, a1.z, a1.w};
            float br[8] = {b0.x, b0.y, b0.z, b0.w, b1.x, b1.y, b1.z, b1.w};
#pragma unroll
            for (int ii = 0; ii < 2; ii++)
#pragma unroll
            for (int i = 0; i < 4; i++)
#pragma unroll
            for (int jj = 0; jj < 2; jj++)
#pragma unroll
            for (int j = 0; j < 4; j++)
                acc[ii][jj][i][j] += ar[ii * 4 + i] * br[jj * 4 + j];
        }

        // ---- Online-softmax epilogue ----
        float4 bc0 = *(const float4*)(biass + c * TC + tx * 4);
        float4 bc1 = *(const float4*)(biass + c * TC + tx * 4 + 64);
        const float bb[2][4] = {{bc0.x, bc0.y, bc0.z, bc0.w},
                                {bc1.x, bc1.y, bc1.z, bc1.w}};
#pragma unroll
        for (int ii = 0; ii < 2; ii++)
#pragma unroll
        for (int i = 0; i < 4; i++) {
            const int rloc = ii * 64 + ty * 4 + i;
            float sv[2][4];
            float cmax = -FLT_MAX;
#pragma unroll
            for (int jj = 0; jj < 2; jj++)
#pragma unroll
            for (int j = 0; j < 4; j++) {
                sv[jj][j] = acc[ii][jj][i][j] + bb[jj][j];
                cmax = fmaxf(cmax, sv[jj][j]);
            }
#pragma unroll
            for (int o = 8; o > 0; o >>= 1)
                cmax = fmaxf(cmax, __shfl_xor_sync(0xffffffffu, cmax, o));

            const float mo  = m_r[ii][i];
            const float mn  = fmaxf(mo, cmax);
            const float fac = __expf(mo - mn);

            float p[2][4];
            float rs = 0.f;
#pragma unroll
            for (int jj = 0; jj < 2; jj++)
#pragma unroll
            for (int j = 0; j < 4; j++) {
                p[jj][j] = __expf(sv[jj][j] - mn);
                rs += p[jj][j];
            }
#pragma unroll
            for (int o = 8; o > 0; o >>= 1)
                rs += __shfl_xor_sync(0xffffffffu, rs, o);

            s_r[ii][i] = s_r[ii][i] * fac + rs;
            m_r[ii][i] = mn;
#pragma unroll
            for (int j = 0; j < 4; j++) oacc[ii][i][j] *= fac;

            float4 p0 = make_float4(p[0][0], p[0][1], p[0][2], p[0][3]);
            float4 p1 = make_float4(p[1][0], p[1][1], p[1][2], p[1][3]);
            *(float4*)(Ps + rloc * 132 + tx * 4)      = p0;
            *(float4*)(Ps + rloc * 132 + tx * 4 + 64) = p1;
            *(float4*)(attnR + (size_t)rloc * SEQ + c * TC + tx * 4)      = p0;
            *(float4*)(attnR + (size_t)rloc * SEQ + c * TC + tx * 4 + 64) = p1;
            if (tx == 0) mh[c * TM + rloc] = mn;
        }
        __syncthreads();

        // ---- AV accumulate: oacc += Ps(128x128) @ Vs(128x64) ----
#pragma unroll 4
        for (int kk = 0; kk < TC; kk++) {
            float4 v4 = *(const float4*)(Vs + kk * 68 + tx * 4);
#pragma unroll
            for (int ii = 0; ii < 2; ii++)
#pragma unroll
            for (int i = 0; i < 4; i++) {
                const float a = Ps[(ii * 64 + ty * 4 + i) * 132 + kk];
                oacc[ii][i][0] += a * v4.x;
                oacc[ii][i][1] += a * v4.y;
                oacc[ii][i][2] += a * v4.z;
                oacc[ii][i][3] += a * v4.w;
            }
        }
    }
    __syncthreads();

    // ---- Phase B: normalize stored attn (reread own writes, L2-hot) ----
    float inv_s[2][4];
#pragma unroll
    for (int ii = 0; ii < 2; ii++)
#pragma unroll
    for (int i = 0; i < 4; i++) inv_s[ii][i] = 1.f / s_r[ii][i];

    for (int c = 0; c < NCH; c++) {
#pragma unroll
        for (int ii = 0; ii < 2; ii++)
#pragma unroll
        for (int i = 0; i < 4; i++) {
            const int rloc = ii * 64 + ty * 4 + i;
            const float corr =
                __expf(mh[c * TM + rloc] - m_r[ii][i]) * inv_s[ii][i];
            float* ap = attnR + (size_t)rloc * SEQ + c * TC + tx * 4;
            float4 u0 = *(const float4*)ap;
            float4 u1 = *(const float4*)(ap + 64);
            u0.x *= corr; u0.y *= corr; u0.z *= corr; u0.w *= corr;
            u1.x *= corr; u1.y *= corr; u1.z *= corr; u1.w *= corr;
            *(float4*)ap        = u0;
            *(float4*)(ap + 64) = u1;
        }
    }

    // ---- Write mid = (AV / s_final) * 1/32, head-interleaved ----
#pragma unroll
    for (int ii = 0; ii < 2; ii++)
#pragma unroll
    for (int i = 0; i < 4; i++) {
        const int r = rowBase + ii * 64 + ty * 4 + i;
        const float f = 0.03125f * inv_s[ii][i];
        float4 v = make_float4(oacc[ii][i][0] * f, oacc[ii][i][1] * f,
                               oacc[ii][i][2] * f, oacc[ii][i][3] * f);
        *(float4*)&mid[((size_t)b * SEQ + r) * HIDN + h * DH + tx * 4] = v;
    }
}

extern "C" void kernel_launch(void* const* d_in, const int* in_sizes, int n_in,
                              void* d_out, int out_size)
{
    const float*         x    = (const float*)d_in[0];
    const unsigned char* mask = (const unsigned char*)d_in[1];
    const float*         Wq   = (const float*)d_in[2];
    const float*         Wk   = (const float*)d_in[3];
    const float*         Wv   = (const float*)d_in[4];
    const float*         Wo   = (const float*)d_in[5];
    float* out = (float*)d_out;

    void *pq, *pk, *pv, *pm;
    cudaGetSymbolAddress(&pq, g_Q);
    cudaGetSymbolAddress(&pk, g_K);
    cudaGetSymbolAddress(&pv, g_V);
    cudaGetSymbolAddress(&pm, g_mid);
    float* q   = (float*)pq;
    float* k   = (float*)pk;
    float* v   = (float*)pv;
    float* mid = (float*)pm;

    float* attn;
    if ((long long)out_size >= OUT_ELEMS + ATTN_ELEMS) {
        attn = out + OUT_ELEMS;
    } else {
        void* pa;
        cudaGetSymbolAddress(&pa, g_attn_fb);
        attn = (float*)pa;
    }

    static bool attr_set = false;
    if (!attr_set) {
        cudaFuncSetAttribute(fused_attn_kernel,
                             cudaFuncAttributeMaxDynamicSharedMemorySize,
                             FUSED_SMEM_BYTES);
        attr_set = true;
    }

    dim3 projGrid(HIDN / BN, MROWS / BM);   // (8, 32)
    gemm128_kernel<1><<<projGrid, 256>>>(x, Wq, q, MROWS, HIDN, DMODEL);
    gemm128_kernel<1><<<projGrid, 256>>>(x, Wk, k, MROWS, HIDN, DMODEL);
    gemm128_kernel<1><<<projGrid, 256>>>(x, Wv, v, MROWS, HIDN, DMODEL);

    fused_attn_kernel<<<dim3(SEQ / TM, BSZ * NH), 256, FUSED_SMEM_BYTES>>>(
        q, k, v, mask, attn, mid);

    gemm128_kernel<0><<<dim3(DMODEL / BN, MROWS / BM), 256>>>(
        mid, Wo, out, MROWS, DMODEL, HIDN);
}

// round 17
// speedup vs baseline: 1.4842x; 1.4137x over previous
#include <cuda_runtime.h>
#include <cuda_bf16.h>
#include <float.h>

// Problem shape (fixed by the dataset)
#define BSZ    2
#define SEQ    2048
#define DMODEL 1024
#define NH     16
#define DH     64
#define HIDN   1024
#define MROWS  (BSZ * SEQ)              // 4096

static const long long OUT_ELEMS  = (long long)BSZ * SEQ * DMODEL;   // 4,194,304
static const long long ATTN_ELEMS = (long long)BSZ * NH * SEQ * SEQ; // 134,217,728

// Scratch (allocation-free rule: __device__ globals)
__device__ float g_Q[BSZ * NH * SEQ * DH];
__device__ float g_K[BSZ * NH * SEQ * DH];
__device__ float g_V[BSZ * NH * SEQ * DH];
__device__ float g_mid[BSZ * SEQ * HIDN];
__device__ float g_attn_fb[BSZ * NH * SEQ * SEQ];

// ============================================================================
// Split-precision bf16 tensor-core GEMM (NT): C = A @ W^T, A[M,K], W[N,K].
// fp32 is split a = a_hi + a_lo (both bf16); D = hi*hi + hi*lo + lo*hi via
// mma.sync.aligned.m16n8k16 (lo*lo dropped, rel err ~2^-18 per product).
// Block tile 128x128, BK=16, 256 threads = 8 warps (4 M x 2 N), each warp
// 32x64 = 2x8 mma tiles. smem: u32 rows of stride 12 (conflict-free for the
// (g=lane>>2, tg=lane&3) fragment pattern), double-buffered.
// MODE 0: C row-major [M,N]
// MODE 1: head-format write C[((b*NH+h)*SEQ+s)*DH + d], m=(b,s), n=(h,d)
// MODE 2: batched per-head scores: blockIdx.z = bh; A,W offset bh*SEQ*DH;
//         C offset bh*SEQ*SEQ (row-major SEQ x SEQ)
// ============================================================================
#define SSTR 12                       // u32 per smem row (8 data + 4 pad)
#define TILE_U32 (128 * SSTR)         // 1536 u32 per (array, buffer)
#define MMA_SMEM_BYTES (2 * 4 * TILE_U32 * 4)  // 49152 B (within default 48KB)

__device__ __forceinline__ void splitpack(float x, float y,
                                          unsigned& hi, unsigned& lo)
{
    __nv_bfloat16 xh = __float2bfloat16_rn(x);
    __nv_bfloat16 yh = __float2bfloat16_rn(y);
    __nv_bfloat16 xl = __float2bfloat16_rn(x - __bfloat162float(xh));
    __nv_bfloat16 yl = __float2bfloat16_rn(y - __bfloat162float(yh));
    hi = ((unsigned)__bfloat16_as_ushort(yh) << 16) | __bfloat16_as_ushort(xh);
    lo = ((unsigned)__bfloat16_as_ushort(yl) << 16) | __bfloat16_as_ushort(xl);
}

__device__ __forceinline__ void mma16816(float* d,
    unsigned a0, unsigned a1, unsigned a2, unsigned a3,
    unsigned b0, unsigned b1)
{
    asm volatile(
        "mma.sync.aligned.m16n8k16.row.col.f32.bf16.bf16.f32 "
        "{%0,%1,%2,%3}, {%4,%5,%6,%7}, {%8,%9}, {%0,%1,%2,%3};"
        : "+f"(d[0]), "+f"(d[1]), "+f"(d[2]), "+f"(d[3])
        : "r"(a0), "r"(a1), "r"(a2), "r"(a3), "r"(b0), "r"(b1));
}

template <int MODE>
__global__ void __launch_bounds__(256) mma_gemm_nt(
    const float* __restrict__ A, const float* __restrict__ W,
    float* __restrict__ C, int M, int N, int K)
{
    if (MODE == 2) {
        const int bh = blockIdx.z;
        A += (size_t)bh * SEQ * DH;
        W += (size_t)bh * SEQ * DH;
        C += (size_t)bh * SEQ * SEQ;
    }

    extern __shared__ __align__(16) unsigned smu[];
    // layout: [buf][0:AH 1:AL 2:WH 3:WL][TILE_U32]

    const int tid  = threadIdx.x;
    const int warp = tid >> 5;
    const int lane = tid & 31;
    const int g    = lane >> 2;
    const int tg   = lane & 3;
    const int wm   = warp & 3;        // 4 warps over M: 32 rows each
    const int wn   = warp >> 2;       // 2 warps over N: 64 cols each
    const int mBase = blockIdx.y * 128;
    const int nBase = blockIdx.x * 128;

    // Loader mapping: 256 threads -> 128 rows x 2 halves of 8 floats
    const int lrow  = tid >> 1;
    const int lhalf = tid & 1;
    const float* Ap = A + (size_t)(mBase + lrow) * K + lhalf * 8;
    const float* Wp = W + (size_t)(nBase + lrow) * K + lhalf * 8;
    const unsigned sbase = lrow * SSTR + lhalf * 4;

    float acc[2][8][4];
#pragma unroll
    for (int mt = 0; mt < 2; mt++)
#pragma unroll
    for (int nt = 0; nt < 8; nt++)
#pragma unroll
    for (int r = 0; r < 4; r++) acc[mt][nt][r] = 0.f;

    // Prologue: chunk 0 -> buffer 0
    {
        float4 fa0 = *(const float4*)Ap;
        float4 fa1 = *(const float4*)(Ap + 4);
        float4 fw0 = *(const float4*)Wp;
        float4 fw1 = *(const float4*)(Wp + 4);
        unsigned h[4], l[4];
        splitpack(fa0.x, fa0.y, h[0], l[0]);
        splitpack(fa0.z, fa0.w, h[1], l[1]);
        splitpack(fa1.x, fa1.y, h[2], l[2]);
        splitpack(fa1.z, fa1.w, h[3], l[3]);
        *(uint4*)(smu + 0 * TILE_U32 + sbase) = make_uint4(h[0], h[1], h[2], h[3]);
        *(uint4*)(smu + 1 * TILE_U32 + sbase) = make_uint4(l[0], l[1], l[2], l[3]);
        splitpack(fw0.x, fw0.y, h[0], l[0]);
        splitpack(fw0.z, fw0.w, h[1], l[1]);
        splitpack(fw1.x, fw1.y, h[2], l[2]);
        splitpack(fw1.z, fw1.w, h[3], l[3]);
        *(uint4*)(smu + 2 * TILE_U32 + sbase) = make_uint4(h[0], h[1], h[2], h[3]);
        *(uint4*)(smu + 3 * TILE_U32 + sbase) = make_uint4(l[0], l[1], l[2], l[3]);
    }
    __syncthreads();

    int buf = 0;
    for (int k0 = 0; k0 < K; k0 += 16) {
        float4 fa0, fa1, fw0, fw1;
        const bool more = (k0 + 16) < K;
        if (more) {
            fa0 = *(const float4*)(Ap + k0 + 16);
            fa1 = *(const float4*)(Ap + k0 + 20);
            fw0 = *(const float4*)(Wp + k0 + 16);
            fw1 = *(const float4*)(Wp + k0 + 20);
        }

        const unsigned* AH = smu + (buf * 4 + 0) * TILE_U32;
        const unsigned* AL = smu + (buf * 4 + 1) * TILE_U32;
        const unsigned* WH = smu + (buf * 4 + 2) * TILE_U32;
        const unsigned* WL = smu + (buf * 4 + 3) * TILE_U32;

        // B fragments for all 8 n-tiles
        unsigned bh0[8], bh1[8], bl0[8], bl1[8];
#pragma unroll
        for (int nt = 0; nt < 8; nt++) {
            const int r = (wn * 64 + nt * 8 + g) * SSTR;
            bh0[nt] = WH[r + tg];
            bh1[nt] = WH[r + tg + 4];
            bl0[nt] = WL[r + tg];
            bl1[nt] = WL[r + tg + 4];
        }
#pragma unroll
        for (int mt = 0; mt < 2; mt++) {
            const int r0 = (wm * 32 + mt * 16 + g) * SSTR;
            const int r1 = r0 + 8 * SSTR;
            const unsigned ah0 = AH[r0 + tg], ah1 = AH[r1 + tg];
            const unsigned ah2 = AH[r0 + tg + 4], ah3 = AH[r1 + tg + 4];
            const unsigned al0 = AL[r0 + tg], al1 = AL[r1 + tg];
            const unsigned al2 = AL[r0 + tg + 4], al3 = AL[r1 + tg + 4];
#pragma unroll
            for (int nt = 0; nt < 8; nt++) {
                mma16816(acc[mt][nt], ah0, ah1, ah2, ah3, bh0[nt], bh1[nt]);
                mma16816(acc[mt][nt], ah0, ah1, ah2, ah3, bl0[nt], bl1[nt]);
                mma16816(acc[mt][nt], al0, al1, al2, al3, bh0[nt], bh1[nt]);
            }
        }

        if (more) {
            const int nb = buf ^ 1;
            unsigned h[4], l[4];
            splitpack(fa0.x, fa0.y, h[0], l[0]);
            splitpack(fa0.z, fa0.w, h[1], l[1]);
            splitpack(fa1.x, fa1.y, h[2], l[2]);
            splitpack(fa1.z, fa1.w, h[3], l[3]);
            *(uint4*)(smu + (nb * 4 + 0) * TILE_U32 + sbase) = make_uint4(h[0], h[1], h[2], h[3]);
            *(uint4*)(smu + (nb * 4 + 1) * TILE_U32 + sbase) = make_uint4(l[0], l[1], l[2], l[3]);
            splitpack(fw0.x, fw0.y, h[0], l[0]);
            splitpack(fw0.z, fw0.w, h[1], l[1]);
            splitpack(fw1.x, fw1.y, h[2], l[2]);
            splitpack(fw1.z, fw1.w, h[3], l[3]);
            *(uint4*)(smu + (nb * 4 + 2) * TILE_U32 + sbase) = make_uint4(h[0], h[1], h[2], h[3]);
            *(uint4*)(smu + (nb * 4 + 3) * TILE_U32 + sbase) = make_uint4(l[0], l[1], l[2], l[3]);
        }
        __syncthreads();
        buf ^= 1;
    }

    // Epilogue: c0=(g,2tg) c1=(g,2tg+1) c2=(g+8,2tg) c3=(g+8,2tg+1)
#pragma unroll
    for (int mt = 0; mt < 2; mt++) {
        const int m0 = mBase + wm * 32 + mt * 16 + g;
        const int m1 = m0 + 8;
#pragma unroll
        for (int nt = 0; nt < 8; nt++) {
            const int n = nBase + wn * 64 + nt * 8 + 2 * tg;
            const float* d = acc[mt][nt];
            if (MODE == 1) {
                const int h_ = n >> 6;
                const int d_ = n & (DH - 1);
                {
                    const int b_ = m0 >> 11, s_ = m0 & (SEQ - 1);
                    float* p = &C[((size_t)(b_ * NH + h_) * SEQ + s_) * DH + d_];
                    p[0] = d[0]; p[1] = d[1];
                }
                {
                    const int b_ = m1 >> 11, s_ = m1 & (SEQ - 1);
                    float* p = &C[((size_t)(b_ * NH + h_) * SEQ + s_) * DH + d_];
                    p[0] = d[2]; p[1] = d[3];
                }
            } else {
                const int ld = (MODE == 2) ? SEQ : N;
                float* p0 = &C[(size_t)m0 * ld + n];
                float* p1 = &C[(size_t)m1 * ld + n];
                p0[0] = d[0]; p0[1] = d[1];
                p1[0] = d[2]; p1[1] = d[3];
            }
        }
    }
}

// ============================================================================
// Softmax, in-place over last dim (SEQ), one block per row. (unchanged, R11)
// ============================================================================
__global__ void __launch_bounds__(256) softmax_kernel(
    float* __restrict__ attn, const unsigned char* __restrict__ mask)
{
    const int row = blockIdx.x;              // 0 .. BSZ*NH*SEQ-1
    const int b   = row >> 15;               // row / (NH*SEQ)
    float* rp = attn + (size_t)row * SEQ;

    __shared__ __align__(16) float bias[SEQ];
    __shared__ float red[8];

    const int stride =
        (mask[0] == 1 && mask[1] == 0 && mask[2] == 0 && mask[3] == 0) ? 4 : 1;
    const unsigned char* mb = mask + (size_t)b * SEQ * stride;

    const int tid = threadIdx.x;
    for (int j = tid; j < SEQ; j += 256)
        bias[j] = mb[(size_t)j * stride] ? 0.f : -FLT_MAX;
    __syncthreads();

    const int j0 = tid << 3;
    float4 u0 = *(const float4*)&rp[j0];
    float4 u1 = *(const float4*)&rp[j0 + 4];
    float4 c0 = *(const float4*)&bias[j0];
    float4 c1 = *(const float4*)&bias[j0 + 4];
    float v[8] = {u0.x + c0.x, u0.y + c0.y, u0.z + c0.z, u0.w + c0.w,
                  u1.x + c1.x, u1.y + c1.y, u1.z + c1.z, u1.w + c1.w};

    float mx = v[0];
#pragma unroll
    for (int i = 1; i < 8; i++) mx = fmaxf(mx, v[i]);
#pragma unroll
    for (int o = 16; o > 0; o >>= 1) mx = fmaxf(mx, __shfl_xor_sync(0xffffffffu, mx, o));
    if ((tid & 31) == 0) red[tid >> 5] = mx;
    __syncthreads();
    float fmx = red[0];
#pragma unroll
    for (int i = 1; i < 8; i++) fmx = fmaxf(fmx, red[i]);

    float sum = 0.f;
#pragma unroll
    for (int i = 0; i < 8; i++) { v[i] = __expf(v[i] - fmx); sum += v[i]; }
#pragma unroll
    for (int o = 16; o > 0; o >>= 1) sum += __shfl_xor_sync(0xffffffffu, sum, o);
    __syncthreads();
    if ((tid & 31) == 0) red[tid >> 5] = sum;
    __syncthreads();
    float tot = 0.f;
#pragma unroll
    for (int i = 0; i < 8; i++) tot += red[i];
    const float inv = 1.f / tot;

    float4 w0 = make_float4(v[0] * inv, v[1] * inv, v[2] * inv, v[3] * inv);
    float4 w1 = make_float4(v[4] * inv, v[5] * inv, v[6] * inv, v[7] * inv);
    *(float4*)&rp[j0]     = w0;
    *(float4*)&rp[j0 + 4] = w1;
}

// ============================================================================
// AV: mid[b][i][h*DH+n] = scale * sum_j attn[bh][i][j] * V[bh][j][n]
// (unchanged, R11: 128x64 tile, BK=16, 8x4 microtile, double-buffered)
// ============================================================================
#define AM 128
#define AN 64
#define AK 16

__global__ void __launch_bounds__(256) av_kernel(
    const float* __restrict__ attn, const float* __restrict__ V,
    float* __restrict__ mid)
{
    const int bh = blockIdx.z;
    const int b  = bh >> 4;
    const int h  = bh & 15;
    const float* A  = attn + (size_t)bh * SEQ * SEQ;
    const float* Vb = V    + (size_t)bh * SEQ * DH;

    __shared__ __align__(16) float As[2][AK][AM];
    __shared__ __align__(16) float Bs[2][AK][AN];

    const int tid   = threadIdx.x;
    const int tx    = tid & 15;
    const int ty    = tid >> 4;
    const int mBase = blockIdx.y * AM;

    const int arow = tid >> 2;
    const int akc  = (tid & 3) << 2;
    const int vrow = tid >> 4;
    const int vcol = (tid & 15) << 2;

    const float* Ap0 = A + (size_t)(mBase + arow) * SEQ + akc;
    const float* Ap1 = Ap0 + (size_t)64 * SEQ;
    const float* Vp  = Vb + (size_t)vrow * DH + vcol;

    float acc[2][4][4] = {};

    {
        float4 a0 = *(const float4*)Ap0;
        float4 a1 = *(const float4*)Ap1;
        float4 vv = *(const float4*)Vp;
        As[0][akc + 0][arow] = a0.x; As[0][akc + 1][arow] = a0.y;
        As[0][akc + 2][arow] = a0.z; As[0][akc + 3][arow] = a0.w;
        As[0][akc + 0][arow + 64] = a1.x; As[0][akc + 1][arow + 64] = a1.y;
        As[0][akc + 2][arow + 64] = a1.z; As[0][akc + 3][arow + 64] = a1.w;
        *(float4*)&Bs[0][vrow][vcol] = vv;
    }
    __syncthreads();

    int buf = 0;
    for (int k0 = 0; k0 < SEQ; k0 += AK) {
        float4 na0, na1, nv;
        const bool more = (k0 + AK) < SEQ;
        if (more) {
            na0 = *(const float4*)(Ap0 + k0 + AK);
            na1 = *(const float4*)(Ap1 + k0 + AK);
            nv  = *(const float4*)(Vp + (size_t)(k0 + AK) * DH);
        }
#pragma unroll
        for (int kk = 0; kk < AK; kk++) {
            float4 a0 = *(const float4*)&As[buf][kk][ty * 4];
            float4 a1 = *(const float4*)&As[buf][kk][ty * 4 + 64];
            float4 bv = *(const float4*)&Bs[buf][kk][tx * 4];
            float ar[8] = {a0.x, a0.y, a0.z, a0.w, a1.x, a1.y, a1.z, a1.w};
            float br[4] = {bv.x, bv.y, bv.z, bv.w};
#pragma unroll
            for (int ii = 0; ii < 2; ii++)
#pragma unroll
            for (int i = 0; i < 4; i++)
#pragma unroll
            for (int j = 0; j < 4; j++)
                acc[ii][i][j] += ar[ii * 4 + i] * br[j];
        }
        if (more) {
            const int nb = buf ^ 1;
            As[nb][akc + 0][arow] = na0.x; As[nb][akc + 1][arow] = na0.y;
            As[nb][akc + 2][arow] = na0.z; As[nb][akc + 3][arow] = na0.w;
            As[nb][akc + 0][arow + 64] = na1.x; As[nb][akc + 1][arow + 64] = na1.y;
            As[nb][akc + 2][arow + 64] = na1.z; As[nb][akc + 3][arow + 64] = na1.w;
            *(float4*)&Bs[nb][vrow][vcol] = nv;
        }
        __syncthreads();
        buf ^= 1;
    }

    const float scale = 0.03125f;  // HID^(-0.5) = 1/32
#pragma unroll
    for (int ii = 0; ii < 2; ii++)
#pragma unroll
    for (int i = 0; i < 4; i++) {
        const int m = mBase + ii * 64 + ty * 4 + i;
        float4 v = make_float4(acc[ii][i][0] * scale, acc[ii][i][1] * scale,
                               acc[ii][i][2] * scale, acc[ii][i][3] * scale);
        *(float4*)&mid[((size_t)b * SEQ + m) * HIDN + h * DH + tx * 4] = v;
    }
}

extern "C" void kernel_launch(void* const* d_in, const int* in_sizes, int n_in,
                              void* d_out, int out_size)
{
    const float*         x    = (const float*)d_in[0];
    const unsigned char* mask = (const unsigned char*)d_in[1];
    const float*         Wq   = (const float*)d_in[2];
    const float*         Wk   = (const float*)d_in[3];
    const float*         Wv   = (const float*)d_in[4];
    const float*         Wo   = (const float*)d_in[5];
    float* out = (float*)d_out;

    void *pq, *pk, *pv, *pm;
    cudaGetSymbolAddress(&pq, g_Q);
    cudaGetSymbolAddress(&pk, g_K);
    cudaGetSymbolAddress(&pv, g_V);
    cudaGetSymbolAddress(&pm, g_mid);
    float* q   = (float*)pq;
    float* k   = (float*)pk;
    float* v   = (float*)pv;
    float* mid = (float*)pm;

    float* attn;
    if ((long long)out_size >= OUT_ELEMS + ATTN_ELEMS) {
        attn = out + OUT_ELEMS;
    } else {
        void* pa;
        cudaGetSymbolAddress(&pa, g_attn_fb);
        attn = (float*)pa;
    }

    // Projections (tensor cores, split-bf16)
    dim3 projGrid(HIDN / 128, MROWS / 128);   // (8, 32)
    mma_gemm_nt<1><<<projGrid, 256, MMA_SMEM_BYTES>>>(x, Wq, q, MROWS, HIDN, DMODEL);
    mma_gemm_nt<1><<<projGrid, 256, MMA_SMEM_BYTES>>>(x, Wk, k, MROWS, HIDN, DMODEL);
    mma_gemm_nt<1><<<projGrid, 256, MMA_SMEM_BYTES>>>(x, Wv, v, MROWS, HIDN, DMODEL);

    // Scores (tensor cores)
    mma_gemm_nt<2><<<dim3(SEQ / 128, SEQ / 128, BSZ * NH), 256, MMA_SMEM_BYTES>>>(
        q, k, attn, SEQ, SEQ, DH);

    softmax_kernel<<<BSZ * NH * SEQ, 256>>>(attn, mask);

    av_kernel<<<dim3(1, SEQ / AM, BSZ * NH), 256>>>(attn, v, mid);

    // Output projection (tensor cores)
    mma_gemm_nt<0><<<dim3(DMODEL / 128, MROWS / 128), 256, MMA_SMEM_BYTES>>>(
        mid, Wo, out, MROWS, DMODEL, HIDN);
}